// round 1
// baseline (speedup 1.0000x reference)
#include <cuda_runtime.h>
#include <cuda_bf16.h>
#include <cstddef>

// ---------------------------------------------------------------------------
// Problem constants
// ---------------------------------------------------------------------------
#define TT   2048
#define BB   2
#define DD   1024
#define HH   16
#define HDIM 64
#define FFD  4096
#define MM   (TT * BB)          // 4096 rows
#define D3   (3 * DD)           // 3072

// ---------------------------------------------------------------------------
// Scratch (device globals; no runtime allocation allowed)
// ---------------------------------------------------------------------------
__device__ float g_qkv [MM * D3];   // [4096, 3072]  q|k|v
__device__ float g_attn[MM * DD];   // attention output
__device__ float g_h   [MM * DD];   // post-LN1 hidden
__device__ float g_ff  [MM * FFD];  // fc1+gelu output
__device__ float g_tmp [MM * DD];   // gemm staging

// ---------------------------------------------------------------------------
// GELU (tanh approximation, matches reference)
// ---------------------------------------------------------------------------
__device__ __forceinline__ float gelu_f(float v) {
    const float c = 0.7978845608028654f;   // sqrt(2/pi)
    float t = tanhf(c * (v + 0.044715f * v * v * v));
    return 0.5f * v * (1.0f + t);
}

// ---------------------------------------------------------------------------
// GEMM: C[M,N] = A[M,K] @ W[N,K]^T + bias   (optionally GELU)
// 128x128 tile, BK=8, 256 threads, 8x8 microtile per thread.
// M,N multiples of 128; K multiple of 8.
// ---------------------------------------------------------------------------
template <int ACT>   // 0 = none, 1 = gelu
__global__ void __launch_bounds__(256)
gemm_kernel(const float* __restrict__ A, const float* __restrict__ W,
            const float* __restrict__ bias, float* __restrict__ C,
            int M, int N, int K)
{
    __shared__ float As[8][128];
    __shared__ float Ws[8][128];

    const int tid = threadIdx.x;
    const int m0  = blockIdx.y * 128;
    const int n0  = blockIdx.x * 128;

    // global loads: thread pair covers one row's 8-float (32B) K-slab
    const int lr = tid >> 1;            // 0..127
    const int lc = (tid & 1) << 2;      // 0 or 4
    const float* Ap = A + (size_t)(m0 + lr) * K + lc;
    const float* Wp = W + (size_t)(n0 + lr) * K + lc;

    const int ty = tid >> 4;            // 0..15 -> 8 rows each
    const int tx = tid & 15;            // 0..15 -> 8 cols each

    float acc[8][8];
#pragma unroll
    for (int i = 0; i < 8; ++i)
#pragma unroll
        for (int j = 0; j < 8; ++j) acc[i][j] = 0.0f;

    for (int k0 = 0; k0 < K; k0 += 8) {
        float4 av = *(const float4*)(Ap + k0);
        float4 wv = *(const float4*)(Wp + k0);
        __syncthreads();
        As[lc + 0][lr] = av.x; As[lc + 1][lr] = av.y;
        As[lc + 2][lr] = av.z; As[lc + 3][lr] = av.w;
        Ws[lc + 0][lr] = wv.x; Ws[lc + 1][lr] = wv.y;
        Ws[lc + 2][lr] = wv.z; Ws[lc + 3][lr] = wv.w;
        __syncthreads();

#pragma unroll
        for (int kk = 0; kk < 8; ++kk) {
            float4 a0 = *(const float4*)&As[kk][ty * 8];
            float4 a1 = *(const float4*)&As[kk][ty * 8 + 4];
            float4 w0 = *(const float4*)&Ws[kk][tx * 8];
            float4 w1 = *(const float4*)&Ws[kk][tx * 8 + 4];
            float a[8] = {a0.x, a0.y, a0.z, a0.w, a1.x, a1.y, a1.z, a1.w};
            float w[8] = {w0.x, w0.y, w0.z, w0.w, w1.x, w1.y, w1.z, w1.w};
#pragma unroll
            for (int i = 0; i < 8; ++i)
#pragma unroll
                for (int j = 0; j < 8; ++j)
                    acc[i][j] = fmaf(a[i], w[j], acc[i][j]);
        }
    }

    float bb[8];
#pragma unroll
    for (int j = 0; j < 8; ++j) bb[j] = bias[n0 + tx * 8 + j];

#pragma unroll
    for (int i = 0; i < 8; ++i) {
        float v[8];
#pragma unroll
        for (int j = 0; j < 8; ++j) {
            float t = acc[i][j] + bb[j];
            if (ACT == 1) t = gelu_f(t);
            v[j] = t;
        }
        float* Crow = C + (size_t)(m0 + ty * 8 + i) * N + n0 + tx * 8;
        *(float4*)(Crow)     = make_float4(v[0], v[1], v[2], v[3]);
        *(float4*)(Crow + 4) = make_float4(v[4], v[5], v[6], v[7]);
    }
}

// ---------------------------------------------------------------------------
// Flash attention (causal), fp32.
// Grid: (qt=32, h=16, b=2). Block: 256 threads.
// BM=64 queries, BN=32 keys per tile, HD=64.
// qkv layout: row = t*BB + b, cols [0:D)=q, [D:2D)=k, [2D:3D)=v
// ---------------------------------------------------------------------------
__global__ void __launch_bounds__(256)
attn_kernel(const float* __restrict__ qkv, float* __restrict__ outp)
{
    const int qt = blockIdx.x;       // query tile
    const int h  = blockIdx.y;
    const int b  = blockIdx.z;

    __shared__ float Qs[64][68];
    __shared__ float Ks[32][68];
    __shared__ float Vs[32][68];
    __shared__ float Ps[64][36];

    const int tid = threadIdx.x;
    const int ty  = tid >> 4;        // 0..15 -> 4 q-rows each
    const int tx  = tid & 15;
    const int r0  = ty * 4;
    const int c0  = tx * 2;          // S cols (2 keys per thread)
    const int d0  = tx * 4;          // O dims (4 per thread)

    const int qoff = h * HDIM;
    const int koff = DD  + h * HDIM;
    const int voff = 2 * DD + h * HDIM;

    // load Q tile, scaled by HD^-0.5
    for (int i = tid; i < 64 * 64; i += 256) {
        int r = i >> 6, d = i & 63;
        int q = qt * 64 + r;
        Qs[r][d] = qkv[(size_t)(q * BB + b) * D3 + qoff + d] * 0.125f;
    }

    float m[4], l[4], O[4][4];
#pragma unroll
    for (int i = 0; i < 4; ++i) {
        m[i] = -1e30f; l[i] = 0.0f;
#pragma unroll
        for (int j = 0; j < 4; ++j) O[i][j] = 0.0f;
    }

    const int ktmax = 2 * qt + 1;    // causal: keys up to (qt+1)*64-1
    for (int kt = 0; kt <= ktmax; ++kt) {
        __syncthreads();             // previous iteration done with Ks/Vs/Ps
        for (int i = tid; i < 32 * 64; i += 256) {
            int r = i >> 6, d = i & 63;
            size_t row = (size_t)((kt * 32 + r) * BB + b) * D3;
            Ks[r][d] = qkv[row + koff + d];
            Vs[r][d] = qkv[row + voff + d];
        }
        __syncthreads();

        // S = Q K^T  (64x32 tile; thread: 4 rows x 2 cols)
        float s[4][2] = {{0.f, 0.f}, {0.f, 0.f}, {0.f, 0.f}, {0.f, 0.f}};
#pragma unroll 8
        for (int d = 0; d < 64; ++d) {
            float b0 = Ks[c0 + 0][d];
            float b1 = Ks[c0 + 1][d];
#pragma unroll
            for (int i = 0; i < 4; ++i) {
                float a = Qs[r0 + i][d];
                s[i][0] = fmaf(a, b0, s[i][0]);
                s[i][1] = fmaf(a, b1, s[i][1]);
            }
        }

        // causal mask (only possible on the last two key tiles)
        if (kt * 32 + 31 > qt * 64) {
#pragma unroll
            for (int i = 0; i < 4; ++i) {
                int q = qt * 64 + r0 + i;
#pragma unroll
                for (int j = 0; j < 2; ++j) {
                    int k = kt * 32 + c0 + j;
                    if (k > q) s[i][j] = -1e30f;
                }
            }
        }

        // online softmax (reduce across the 16 tx lanes; same half-warp)
#pragma unroll
        for (int i = 0; i < 4; ++i) {
            float mt = fmaxf(s[i][0], s[i][1]);
#pragma unroll
            for (int o = 1; o < 16; o <<= 1)
                mt = fmaxf(mt, __shfl_xor_sync(0xffffffffu, mt, o));
            float mnew  = fmaxf(m[i], mt);
            float alpha = __expf(m[i] - mnew);
            float p0 = __expf(s[i][0] - mnew);
            float p1 = __expf(s[i][1] - mnew);
            Ps[r0 + i][c0 + 0] = p0;
            Ps[r0 + i][c0 + 1] = p1;
            float rs = p0 + p1;
#pragma unroll
            for (int o = 1; o < 16; o <<= 1)
                rs += __shfl_xor_sync(0xffffffffu, rs, o);
            l[i] = l[i] * alpha + rs;
            m[i] = mnew;
#pragma unroll
            for (int j = 0; j < 4; ++j) O[i][j] *= alpha;
        }
        __syncthreads();

        // O += P V  (thread: 4 rows x 4 dims)
#pragma unroll 4
        for (int k = 0; k < 32; ++k) {
            float b0 = Vs[k][d0 + 0];
            float b1 = Vs[k][d0 + 1];
            float b2 = Vs[k][d0 + 2];
            float b3 = Vs[k][d0 + 3];
#pragma unroll
            for (int i = 0; i < 4; ++i) {
                float a = Ps[r0 + i][k];
                O[i][0] = fmaf(a, b0, O[i][0]);
                O[i][1] = fmaf(a, b1, O[i][1]);
                O[i][2] = fmaf(a, b2, O[i][2]);
                O[i][3] = fmaf(a, b3, O[i][3]);
            }
        }
    }

    // epilogue: normalize and store
#pragma unroll
    for (int i = 0; i < 4; ++i) {
        float inv = 1.0f / l[i];
        int q = qt * 64 + r0 + i;
        float* op = outp + (size_t)(q * BB + b) * DD + h * HDIM + d0;
        *(float4*)op = make_float4(O[i][0] * inv, O[i][1] * inv,
                                   O[i][2] * inv, O[i][3] * inv);
    }
}

// ---------------------------------------------------------------------------
// Residual add + LayerNorm over D=1024. One block (256 thr) per row.
// out = LN(y + res) * g + b
// ---------------------------------------------------------------------------
__global__ void __launch_bounds__(256)
add_ln_kernel(const float* __restrict__ y, const float* __restrict__ res,
              const float* __restrict__ g, const float* __restrict__ beta,
              float* __restrict__ out)
{
    const int row = blockIdx.x;
    const int tid = threadIdx.x;

    float4 a = ((const float4*)(y   + (size_t)row * DD))[tid];
    float4 r = ((const float4*)(res + (size_t)row * DD))[tid];
    float v0 = a.x + r.x, v1 = a.y + r.y, v2 = a.z + r.z, v3 = a.w + r.w;

    float s  = v0 + v1 + v2 + v3;
    float ss = v0 * v0 + v1 * v1 + v2 * v2 + v3 * v3;

#pragma unroll
    for (int o = 16; o > 0; o >>= 1) {
        s  += __shfl_xor_sync(0xffffffffu, s,  o);
        ss += __shfl_xor_sync(0xffffffffu, ss, o);
    }
    __shared__ float2 red[8];
    if ((tid & 31) == 0) red[tid >> 5] = make_float2(s, ss);
    __syncthreads();
    float sx = 0.f, sxx = 0.f;
#pragma unroll
    for (int i = 0; i < 8; ++i) { sx += red[i].x; sxx += red[i].y; }

    const float invD = 1.0f / (float)DD;
    float mean = sx * invD;
    float var  = fmaxf(sxx * invD - mean * mean, 0.0f);
    float rstd = rsqrtf(var + 1e-5f);

    float4 gg = ((const float4*)g)[tid];
    float4 bb = ((const float4*)beta)[tid];
    float4 o;
    o.x = (v0 - mean) * rstd * gg.x + bb.x;
    o.y = (v1 - mean) * rstd * gg.y + bb.y;
    o.z = (v2 - mean) * rstd * gg.z + bb.z;
    o.w = (v3 - mean) * rstd * gg.w + bb.w;
    ((float4*)(out + (size_t)row * DD))[tid] = o;
}

// ---------------------------------------------------------------------------
// Launch
// ---------------------------------------------------------------------------
extern "C" void kernel_launch(void* const* d_in, const int* in_sizes, int n_in,
                              void* d_out, int out_size)
{
    const float* x         = (const float*)d_in[0];
    // d_in[1] = attn_mask (structurally causal; applied analytically)
    const float* in_proj_w = (const float*)d_in[2];
    const float* in_proj_b = (const float*)d_in[3];
    const float* out_w     = (const float*)d_in[4];
    const float* out_b     = (const float*)d_in[5];
    const float* fc1_w     = (const float*)d_in[6];
    const float* fc1_b     = (const float*)d_in[7];
    const float* fc2_w     = (const float*)d_in[8];
    const float* fc2_b     = (const float*)d_in[9];
    const float* ln1_g     = (const float*)d_in[10];
    const float* ln1_b     = (const float*)d_in[11];
    const float* ln2_g     = (const float*)d_in[12];
    const float* ln2_b     = (const float*)d_in[13];
    float* out = (float*)d_out;

    float *qkv, *attn, *h, *ff, *tmp;
    cudaGetSymbolAddress((void**)&qkv,  g_qkv);
    cudaGetSymbolAddress((void**)&attn, g_attn);
    cudaGetSymbolAddress((void**)&h,    g_h);
    cudaGetSymbolAddress((void**)&ff,   g_ff);
    cudaGetSymbolAddress((void**)&tmp,  g_tmp);

    // 1) fused QKV projection: [4096,3072]
    gemm_kernel<0><<<dim3(D3 / 128, MM / 128), 256>>>(
        x, in_proj_w, in_proj_b, qkv, MM, D3, DD);

    // 2) causal flash attention -> [4096,1024]
    attn_kernel<<<dim3(TT / 64, HH, BB), 256>>>(qkv, attn);

    // 3) output projection
    gemm_kernel<0><<<dim3(DD / 128, MM / 128), 256>>>(
        attn, out_w, out_b, tmp, MM, DD, DD);

    // 4) h = LN1(x + attn_proj)
    add_ln_kernel<<<MM, 256>>>(tmp, x, ln1_g, ln1_b, h);

    // 5) fc1 + gelu: [4096,4096]
    gemm_kernel<1><<<dim3(FFD / 128, MM / 128), 256>>>(
        h, fc1_w, fc1_b, ff, MM, FFD, DD);

    // 6) fc2: [4096,1024]
    gemm_kernel<0><<<dim3(DD / 128, MM / 128), 256>>>(
        ff, fc2_w, fc2_b, tmp, MM, DD, FFD);

    // 7) out = LN2(h + ff2)
    add_ln_kernel<<<MM, 256>>>(tmp, h, ln2_g, ln2_b, out);
}

// round 2
// speedup vs baseline: 2.0230x; 2.0230x over previous
#include <cuda_runtime.h>
#include <cuda_bf16.h>
#include <cstdint>
#include <cstddef>

// ---------------------------------------------------------------------------
// Problem constants
// ---------------------------------------------------------------------------
#define TT   2048
#define BB   2
#define DD   1024
#define HH   16
#define HDIM 64
#define FFD  4096
#define MM   (TT * BB)          // 4096 rows
#define D3   (3 * DD)           // 3072

// ---------------------------------------------------------------------------
// Scratch (device globals; no runtime allocation allowed)
// ---------------------------------------------------------------------------
__device__ float g_qkv [MM * D3];   // [4096, 3072]  q|k|v
__device__ float g_attn[MM * DD];   // attention output
__device__ float g_h   [MM * DD];   // post-LN1 hidden
__device__ float g_ff  [MM * FFD];  // fc1+gelu output
__device__ float g_tmp [MM * DD];   // gemm staging

// ---------------------------------------------------------------------------
// GELU (tanh approximation, matches reference)
// ---------------------------------------------------------------------------
__device__ __forceinline__ float gelu_f(float v) {
    const float c = 0.7978845608028654f;   // sqrt(2/pi)
    float t = tanhf(c * (v + 0.044715f * v * v * v));
    return 0.5f * v * (1.0f + t);
}

__device__ __forceinline__ uint32_t f2tf32(float f) {
    uint32_t u;
    asm("cvt.rna.tf32.f32 %0, %1;" : "=r"(u) : "f"(f));
    return u;
}

// ---------------------------------------------------------------------------
// tf32 tensor-core GEMM: C[M,N] = A[M,K] @ W[N,K]^T + bias (opt. GELU)
// 128x128 tile, BK=32, 256 threads (8 warps, each 64x32 via m16n8k8 MMAs).
// Double-buffered smem, padded stride 36 (conflict-free fragment loads).
// M,N multiples of 128; K multiple of 32.
// ---------------------------------------------------------------------------
#define BK  32
#define LDA 36
#define GEMM_SMEM (2 * 2 * 128 * LDA * 4)   // 73728 bytes

template <int ACT>   // 0 = none, 1 = gelu
__global__ void __launch_bounds__(256)
gemm_tf32(const float* __restrict__ A, const float* __restrict__ W,
          const float* __restrict__ bias, float* __restrict__ C,
          int M, int N, int K)
{
    extern __shared__ uint32_t sm[];
    uint32_t* As = sm;                    // [2][128*LDA]
    uint32_t* Ws = sm + 2 * 128 * LDA;    // [2][128*LDA]

    const int tid  = threadIdx.x;
    const int m0   = blockIdx.y * 128;
    const int n0   = blockIdx.x * 128;
    const int warp = tid >> 5, lane = tid & 31;
    const int gid  = lane >> 2, tig = lane & 3;   // mma lane decomposition
    const int wm   = (warp & 1) * 64;             // warp m-offset in tile
    const int wn   = (warp >> 1) * 32;            // warp n-offset in tile

    float acc[4][4][4];
#pragma unroll
    for (int i = 0; i < 4; ++i)
#pragma unroll
        for (int j = 0; j < 4; ++j)
#pragma unroll
            for (int c = 0; c < 4; ++c) acc[i][j][c] = 0.0f;

    // global-load assignment: 4 float4 per thread per operand
    const int rb = tid >> 3;            // 0..31
    const int cc = (tid & 7) * 4;       // 0,4,...,28
    const float* Ag = A + (size_t)(m0 + rb) * K + cc;
    const float* Wg = W + (size_t)(n0 + rb) * K + cc;

    float4 ra[4], rw[4];

    auto LDG = [&](int k0) {
#pragma unroll
        for (int i = 0; i < 4; ++i) {
            ra[i] = *(const float4*)(Ag + (size_t)(32 * i) * K + k0);
            rw[i] = *(const float4*)(Wg + (size_t)(32 * i) * K + k0);
        }
    };
    auto STS = [&](int buf) {
        uint32_t* Ab = As + buf * 128 * LDA;
        uint32_t* Wb = Ws + buf * 128 * LDA;
#pragma unroll
        for (int i = 0; i < 4; ++i) {
            int r = rb + 32 * i;
            uint4 ua = make_uint4(f2tf32(ra[i].x), f2tf32(ra[i].y),
                                  f2tf32(ra[i].z), f2tf32(ra[i].w));
            *(uint4*)(Ab + r * LDA + cc) = ua;
            uint4 uw = make_uint4(f2tf32(rw[i].x), f2tf32(rw[i].y),
                                  f2tf32(rw[i].z), f2tf32(rw[i].w));
            *(uint4*)(Wb + r * LDA + cc) = uw;
        }
    };
    auto COMPUTE = [&](int buf) {
        const uint32_t* Ab = As + buf * 128 * LDA;
        const uint32_t* Wb = Ws + buf * 128 * LDA;
#pragma unroll
        for (int k8 = 0; k8 < BK; k8 += 8) {
            uint32_t af[4][4], bf[4][2];
#pragma unroll
            for (int mi = 0; mi < 4; ++mi) {
                const uint32_t* p = Ab + (wm + mi * 16 + gid) * LDA + k8 + tig;
                af[mi][0] = p[0];
                af[mi][1] = p[8 * LDA];
                af[mi][2] = p[4];
                af[mi][3] = p[8 * LDA + 4];
            }
#pragma unroll
            for (int ni = 0; ni < 4; ++ni) {
                const uint32_t* p = Wb + (wn + ni * 8 + gid) * LDA + k8 + tig;
                bf[ni][0] = p[0];
                bf[ni][1] = p[4];
            }
#pragma unroll
            for (int mi = 0; mi < 4; ++mi)
#pragma unroll
                for (int ni = 0; ni < 4; ++ni) {
                    asm volatile(
                        "mma.sync.aligned.m16n8k8.row.col.f32.tf32.tf32.f32 "
                        "{%0,%1,%2,%3}, {%4,%5,%6,%7}, {%8,%9}, {%0,%1,%2,%3};\n"
                        : "+f"(acc[mi][ni][0]), "+f"(acc[mi][ni][1]),
                          "+f"(acc[mi][ni][2]), "+f"(acc[mi][ni][3])
                        : "r"(af[mi][0]), "r"(af[mi][1]),
                          "r"(af[mi][2]), "r"(af[mi][3]),
                          "r"(bf[ni][0]), "r"(bf[ni][1]));
                }
        }
    };

    const int KT = K / BK;
    LDG(0);
    STS(0);
    __syncthreads();
    for (int kt = 0; kt < KT; ++kt) {
        if (kt + 1 < KT) LDG((kt + 1) * BK);
        COMPUTE(kt & 1);
        if (kt + 1 < KT) STS((kt + 1) & 1);
        __syncthreads();
    }

    // epilogue: bias (+gelu) and store
#pragma unroll
    for (int mi = 0; mi < 4; ++mi) {
#pragma unroll
        for (int ni = 0; ni < 4; ++ni) {
            int col = n0 + wn + ni * 8 + 2 * tig;
            float b0 = bias[col], b1 = bias[col + 1];
            int row = m0 + wm + mi * 16 + gid;
            float v0 = acc[mi][ni][0] + b0;
            float v1 = acc[mi][ni][1] + b1;
            float v2 = acc[mi][ni][2] + b0;
            float v3 = acc[mi][ni][3] + b1;
            if (ACT == 1) {
                v0 = gelu_f(v0); v1 = gelu_f(v1);
                v2 = gelu_f(v2); v3 = gelu_f(v3);
            }
            *(float2*)(C + (size_t)row * N + col)       = make_float2(v0, v1);
            *(float2*)(C + (size_t)(row + 8) * N + col) = make_float2(v2, v3);
        }
    }
}

// ---------------------------------------------------------------------------
// Flash attention (causal), fp32. Unchanged from R1 (proven correct).
// Grid: (qt=32, h=16, b=2). Block: 256 threads.
// ---------------------------------------------------------------------------
__global__ void __launch_bounds__(256)
attn_kernel(const float* __restrict__ qkv, float* __restrict__ outp)
{
    const int qt = blockIdx.x;
    const int h  = blockIdx.y;
    const int b  = blockIdx.z;

    __shared__ float Qs[64][68];
    __shared__ float Ks[32][68];
    __shared__ float Vs[32][68];
    __shared__ float Ps[64][36];

    const int tid = threadIdx.x;
    const int ty  = tid >> 4;
    const int tx  = tid & 15;
    const int r0  = ty * 4;
    const int c0  = tx * 2;
    const int d0  = tx * 4;

    const int qoff = h * HDIM;
    const int koff = DD  + h * HDIM;
    const int voff = 2 * DD + h * HDIM;

    for (int i = tid; i < 64 * 64; i += 256) {
        int r = i >> 6, d = i & 63;
        int q = qt * 64 + r;
        Qs[r][d] = qkv[(size_t)(q * BB + b) * D3 + qoff + d] * 0.125f;
    }

    float m[4], l[4], O[4][4];
#pragma unroll
    for (int i = 0; i < 4; ++i) {
        m[i] = -1e30f; l[i] = 0.0f;
#pragma unroll
        for (int j = 0; j < 4; ++j) O[i][j] = 0.0f;
    }

    const int ktmax = 2 * qt + 1;
    for (int kt = 0; kt <= ktmax; ++kt) {
        __syncthreads();
        for (int i = tid; i < 32 * 64; i += 256) {
            int r = i >> 6, d = i & 63;
            size_t row = (size_t)((kt * 32 + r) * BB + b) * D3;
            Ks[r][d] = qkv[row + koff + d];
            Vs[r][d] = qkv[row + voff + d];
        }
        __syncthreads();

        float s[4][2] = {{0.f, 0.f}, {0.f, 0.f}, {0.f, 0.f}, {0.f, 0.f}};
#pragma unroll 8
        for (int d = 0; d < 64; ++d) {
            float b0 = Ks[c0 + 0][d];
            float b1 = Ks[c0 + 1][d];
#pragma unroll
            for (int i = 0; i < 4; ++i) {
                float a = Qs[r0 + i][d];
                s[i][0] = fmaf(a, b0, s[i][0]);
                s[i][1] = fmaf(a, b1, s[i][1]);
            }
        }

        if (kt * 32 + 31 > qt * 64) {
#pragma unroll
            for (int i = 0; i < 4; ++i) {
                int q = qt * 64 + r0 + i;
#pragma unroll
                for (int j = 0; j < 2; ++j) {
                    int k = kt * 32 + c0 + j;
                    if (k > q) s[i][j] = -1e30f;
                }
            }
        }

#pragma unroll
        for (int i = 0; i < 4; ++i) {
            float mt = fmaxf(s[i][0], s[i][1]);
#pragma unroll
            for (int o = 1; o < 16; o <<= 1)
                mt = fmaxf(mt, __shfl_xor_sync(0xffffffffu, mt, o));
            float mnew  = fmaxf(m[i], mt);
            float alpha = __expf(m[i] - mnew);
            float p0 = __expf(s[i][0] - mnew);
            float p1 = __expf(s[i][1] - mnew);
            Ps[r0 + i][c0 + 0] = p0;
            Ps[r0 + i][c0 + 1] = p1;
            float rs = p0 + p1;
#pragma unroll
            for (int o = 1; o < 16; o <<= 1)
                rs += __shfl_xor_sync(0xffffffffu, rs, o);
            l[i] = l[i] * alpha + rs;
            m[i] = mnew;
#pragma unroll
            for (int j = 0; j < 4; ++j) O[i][j] *= alpha;
        }
        __syncthreads();

#pragma unroll 4
        for (int k = 0; k < 32; ++k) {
            float b0 = Vs[k][d0 + 0];
            float b1 = Vs[k][d0 + 1];
            float b2 = Vs[k][d0 + 2];
            float b3 = Vs[k][d0 + 3];
#pragma unroll
            for (int i = 0; i < 4; ++i) {
                float a = Ps[r0 + i][k];
                O[i][0] = fmaf(a, b0, O[i][0]);
                O[i][1] = fmaf(a, b1, O[i][1]);
                O[i][2] = fmaf(a, b2, O[i][2]);
                O[i][3] = fmaf(a, b3, O[i][3]);
            }
        }
    }

#pragma unroll
    for (int i = 0; i < 4; ++i) {
        float inv = 1.0f / l[i];
        int q = qt * 64 + r0 + i;
        float* op = outp + (size_t)(q * BB + b) * DD + h * HDIM + d0;
        *(float4*)op = make_float4(O[i][0] * inv, O[i][1] * inv,
                                   O[i][2] * inv, O[i][3] * inv);
    }
}

// ---------------------------------------------------------------------------
// Residual add + LayerNorm over D=1024. One block (256 thr) per row.
// ---------------------------------------------------------------------------
__global__ void __launch_bounds__(256)
add_ln_kernel(const float* __restrict__ y, const float* __restrict__ res,
              const float* __restrict__ g, const float* __restrict__ beta,
              float* __restrict__ out)
{
    const int row = blockIdx.x;
    const int tid = threadIdx.x;

    float4 a = ((const float4*)(y   + (size_t)row * DD))[tid];
    float4 r = ((const float4*)(res + (size_t)row * DD))[tid];
    float v0 = a.x + r.x, v1 = a.y + r.y, v2 = a.z + r.z, v3 = a.w + r.w;

    float s  = v0 + v1 + v2 + v3;
    float ss = v0 * v0 + v1 * v1 + v2 * v2 + v3 * v3;

#pragma unroll
    for (int o = 16; o > 0; o >>= 1) {
        s  += __shfl_xor_sync(0xffffffffu, s,  o);
        ss += __shfl_xor_sync(0xffffffffu, ss, o);
    }
    __shared__ float2 red[8];
    if ((tid & 31) == 0) red[tid >> 5] = make_float2(s, ss);
    __syncthreads();
    float sx = 0.f, sxx = 0.f;
#pragma unroll
    for (int i = 0; i < 8; ++i) { sx += red[i].x; sxx += red[i].y; }

    const float invD = 1.0f / (float)DD;
    float mean = sx * invD;
    float var  = fmaxf(sxx * invD - mean * mean, 0.0f);
    float rstd = rsqrtf(var + 1e-5f);

    float4 gg = ((const float4*)g)[tid];
    float4 bb = ((const float4*)beta)[tid];
    float4 o;
    o.x = (v0 - mean) * rstd * gg.x + bb.x;
    o.y = (v1 - mean) * rstd * gg.y + bb.y;
    o.z = (v2 - mean) * rstd * gg.z + bb.z;
    o.w = (v3 - mean) * rstd * gg.w + bb.w;
    ((float4*)(out + (size_t)row * DD))[tid] = o;
}

// ---------------------------------------------------------------------------
// Launch
// ---------------------------------------------------------------------------
extern "C" void kernel_launch(void* const* d_in, const int* in_sizes, int n_in,
                              void* d_out, int out_size)
{
    const float* x         = (const float*)d_in[0];
    // d_in[1] = attn_mask (structurally causal; applied analytically)
    const float* in_proj_w = (const float*)d_in[2];
    const float* in_proj_b = (const float*)d_in[3];
    const float* out_w     = (const float*)d_in[4];
    const float* out_b     = (const float*)d_in[5];
    const float* fc1_w     = (const float*)d_in[6];
    const float* fc1_b     = (const float*)d_in[7];
    const float* fc2_w     = (const float*)d_in[8];
    const float* fc2_b     = (const float*)d_in[9];
    const float* ln1_g     = (const float*)d_in[10];
    const float* ln1_b     = (const float*)d_in[11];
    const float* ln2_g     = (const float*)d_in[12];
    const float* ln2_b     = (const float*)d_in[13];
    float* out = (float*)d_out;

    float *qkv, *attn, *h, *ff, *tmp;
    cudaGetSymbolAddress((void**)&qkv,  g_qkv);
    cudaGetSymbolAddress((void**)&attn, g_attn);
    cudaGetSymbolAddress((void**)&h,    g_h);
    cudaGetSymbolAddress((void**)&ff,   g_ff);
    cudaGetSymbolAddress((void**)&tmp,  g_tmp);

    cudaFuncSetAttribute(gemm_tf32<0>,
                         cudaFuncAttributeMaxDynamicSharedMemorySize, GEMM_SMEM);
    cudaFuncSetAttribute(gemm_tf32<1>,
                         cudaFuncAttributeMaxDynamicSharedMemorySize, GEMM_SMEM);

    // 1) fused QKV projection: [4096,3072]
    gemm_tf32<0><<<dim3(D3 / 128, MM / 128), 256, GEMM_SMEM>>>(
        x, in_proj_w, in_proj_b, qkv, MM, D3, DD);

    // 2) causal flash attention -> [4096,1024]
    attn_kernel<<<dim3(TT / 64, HH, BB), 256>>>(qkv, attn);

    // 3) output projection
    gemm_tf32<0><<<dim3(DD / 128, MM / 128), 256, GEMM_SMEM>>>(
        attn, out_w, out_b, tmp, MM, DD, DD);

    // 4) h = LN1(x + attn_proj)
    add_ln_kernel<<<MM, 256>>>(tmp, x, ln1_g, ln1_b, h);

    // 5) fc1 + gelu: [4096,4096]
    gemm_tf32<1><<<dim3(FFD / 128, MM / 128), 256, GEMM_SMEM>>>(
        h, fc1_w, fc1_b, ff, MM, FFD, DD);

    // 6) fc2: [4096,1024]
    gemm_tf32<0><<<dim3(DD / 128, MM / 128), 256, GEMM_SMEM>>>(
        ff, fc2_w, fc2_b, tmp, MM, DD, FFD);

    // 7) out = LN2(h + ff2)
    add_ln_kernel<<<MM, 256>>>(tmp, h, ln2_g, ln2_b, out);
}

// round 3
// speedup vs baseline: 2.5181x; 1.2448x over previous
#include <cuda_runtime.h>
#include <cuda_bf16.h>
#include <cstdint>
#include <cstddef>

// ---------------------------------------------------------------------------
// Problem constants
// ---------------------------------------------------------------------------
#define TT   2048
#define BB   2
#define DD   1024
#define HH   16
#define HDIM 64
#define FFD  4096
#define MM   (TT * BB)          // 4096 rows
#define D3   (3 * DD)           // 3072

// ---------------------------------------------------------------------------
// Scratch (device globals; no runtime allocation allowed)
// ---------------------------------------------------------------------------
__device__ float g_qkv [MM * D3];
__device__ float g_attn[MM * DD];
__device__ float g_h   [MM * DD];
__device__ float g_ff  [MM * FFD];
__device__ float g_tmp [MM * DD];

__device__ __forceinline__ float gelu_f(float v) {
    const float c = 0.7978845608028654f;   // sqrt(2/pi)
    float t = tanhf(c * (v + 0.044715f * v * v * v));
    return 0.5f * v * (1.0f + t);
}

__device__ __forceinline__ uint32_t f2tf32(float f) {
    uint32_t u;
    asm("cvt.rna.tf32.f32 %0, %1;" : "=r"(u) : "f"(f));
    return u;
}

#define MMA_TF32(d0,d1,d2,d3,a0,a1,a2,a3,b0,b1)                               \
    asm volatile(                                                             \
        "mma.sync.aligned.m16n8k8.row.col.f32.tf32.tf32.f32 "                 \
        "{%0,%1,%2,%3}, {%4,%5,%6,%7}, {%8,%9}, {%0,%1,%2,%3};\n"             \
        : "+f"(d0), "+f"(d1), "+f"(d2), "+f"(d3)                              \
        : "r"(a0), "r"(a1), "r"(a2), "r"(a3), "r"(b0), "r"(b1))

// ---------------------------------------------------------------------------
// tf32 tensor-core GEMM: C[M,N] = A[M,K] @ W[N,K]^T + bias (opt. GELU)
// 128x128 tile, BK=16, 256 threads (8 warps x 64x32), double-buffered,
// 2 CTAs/SM (40KB smem, <=128 regs).
// ---------------------------------------------------------------------------
#define BK  16
#define LDA 20
#define GEMM_SMEM (2 * 2 * 128 * LDA * 4)   // 40960 bytes

template <int ACT>
__global__ void __launch_bounds__(256, 2)
gemm_tf32(const float* __restrict__ A, const float* __restrict__ W,
          const float* __restrict__ bias, float* __restrict__ C,
          int M, int N, int K)
{
    extern __shared__ uint32_t sm[];
    uint32_t* As = sm;                    // [2][128*LDA]
    uint32_t* Ws = sm + 2 * 128 * LDA;

    const int tid  = threadIdx.x;
    const int m0   = blockIdx.y * 128;
    const int n0   = blockIdx.x * 128;
    const int warp = tid >> 5, lane = tid & 31;
    const int gid  = lane >> 2, tig = lane & 3;
    const int wm   = (warp & 1) * 64;
    const int wn   = (warp >> 1) * 32;

    float acc[4][4][4];
#pragma unroll
    for (int i = 0; i < 4; ++i)
#pragma unroll
        for (int j = 0; j < 4; ++j)
#pragma unroll
            for (int c = 0; c < 4; ++c) acc[i][j][c] = 0.0f;

    // global loads: one row per thread, 16 floats (2 x float4)
    const int lr = tid >> 1;
    const int lc = (tid & 1) << 3;        // 0 or 8
    const float* Ag = A + (size_t)(m0 + lr) * K + lc;
    const float* Wg = W + (size_t)(n0 + lr) * K + lc;

    float4 ra[2], rw[2];

    auto LDG = [&](int k0) {
        ra[0] = *(const float4*)(Ag + k0);
        ra[1] = *(const float4*)(Ag + k0 + 4);
        rw[0] = *(const float4*)(Wg + k0);
        rw[1] = *(const float4*)(Wg + k0 + 4);
    };
    auto STS = [&](int buf) {
        uint32_t* Ab = As + buf * 128 * LDA + lr * LDA + lc;
        uint32_t* Wb = Ws + buf * 128 * LDA + lr * LDA + lc;
        *(uint4*)(Ab)     = make_uint4(f2tf32(ra[0].x), f2tf32(ra[0].y),
                                       f2tf32(ra[0].z), f2tf32(ra[0].w));
        *(uint4*)(Ab + 4) = make_uint4(f2tf32(ra[1].x), f2tf32(ra[1].y),
                                       f2tf32(ra[1].z), f2tf32(ra[1].w));
        *(uint4*)(Wb)     = make_uint4(f2tf32(rw[0].x), f2tf32(rw[0].y),
                                       f2tf32(rw[0].z), f2tf32(rw[0].w));
        *(uint4*)(Wb + 4) = make_uint4(f2tf32(rw[1].x), f2tf32(rw[1].y),
                                       f2tf32(rw[1].z), f2tf32(rw[1].w));
    };
    auto COMPUTE = [&](int buf) {
        const uint32_t* Ab = As + buf * 128 * LDA;
        const uint32_t* Wb = Ws + buf * 128 * LDA;
#pragma unroll
        for (int k8 = 0; k8 < BK; k8 += 8) {
            uint32_t af[4][4], bf[4][2];
#pragma unroll
            for (int mi = 0; mi < 4; ++mi) {
                const uint32_t* p = Ab + (wm + mi * 16 + gid) * LDA + k8 + tig;
                af[mi][0] = p[0];
                af[mi][1] = p[8 * LDA];
                af[mi][2] = p[4];
                af[mi][3] = p[8 * LDA + 4];
            }
#pragma unroll
            for (int ni = 0; ni < 4; ++ni) {
                const uint32_t* p = Wb + (wn + ni * 8 + gid) * LDA + k8 + tig;
                bf[ni][0] = p[0];
                bf[ni][1] = p[4];
            }
#pragma unroll
            for (int mi = 0; mi < 4; ++mi)
#pragma unroll
                for (int ni = 0; ni < 4; ++ni)
                    MMA_TF32(acc[mi][ni][0], acc[mi][ni][1],
                             acc[mi][ni][2], acc[mi][ni][3],
                             af[mi][0], af[mi][1], af[mi][2], af[mi][3],
                             bf[ni][0], bf[ni][1]);
        }
    };

    const int KT = K / BK;
    LDG(0);
    STS(0);
    __syncthreads();
    for (int kt = 0; kt < KT; ++kt) {
        if (kt + 1 < KT) LDG((kt + 1) * BK);
        COMPUTE(kt & 1);
        if (kt + 1 < KT) STS((kt + 1) & 1);
        __syncthreads();
    }

#pragma unroll
    for (int mi = 0; mi < 4; ++mi) {
#pragma unroll
        for (int ni = 0; ni < 4; ++ni) {
            int col = n0 + wn + ni * 8 + 2 * tig;
            float b0 = bias[col], b1 = bias[col + 1];
            int row = m0 + wm + mi * 16 + gid;
            float v0 = acc[mi][ni][0] + b0;
            float v1 = acc[mi][ni][1] + b1;
            float v2 = acc[mi][ni][2] + b0;
            float v3 = acc[mi][ni][3] + b1;
            if (ACT == 1) {
                v0 = gelu_f(v0); v1 = gelu_f(v1);
                v2 = gelu_f(v2); v3 = gelu_f(v3);
            }
            *(float2*)(C + (size_t)row * N + col)       = make_float2(v0, v1);
            *(float2*)(C + (size_t)(row + 8) * N + col) = make_float2(v2, v3);
        }
    }
}

// ---------------------------------------------------------------------------
// Flash attention (causal) on tf32 tensor cores.
// Grid (qt=32, h=16, b=2), 128 threads (4 warps). BM=64, BN=64, HD=64.
// Warp w owns q-rows [w*16, w*16+16). Dynamic smem 70656 B.
// ---------------------------------------------------------------------------
#define ATTN_SMEM ((64 * 68 * 3 + 64 * 72) * 4)

__global__ void __launch_bounds__(128)
attn_mma(const float* __restrict__ qkv, float* __restrict__ outp)
{
    extern __shared__ uint32_t asm_[];
    uint32_t* Qs = asm_;                    // [64][68]
    uint32_t* Ks = Qs + 64 * 68;            // [64][68]
    uint32_t* Ps = Ks + 64 * 68;            // [64][68]
    uint32_t* Vs = Ps + 64 * 68;            // [64][72]

    const int qt = blockIdx.x, h = blockIdx.y, b = blockIdx.z;
    const int tid = threadIdx.x;
    const int warp = tid >> 5, lane = tid & 31;
    const int gid = lane >> 2, tig = lane & 3;
    const int wr = warp * 16;

    const int qoff = h * HDIM;
    const int koff = DD + h * HDIM;
    const int voff = 2 * DD + h * HDIM;

    // load Q tile (scaled by 0.125, tf32-rounded)
    for (int i = tid; i < 64 * 16; i += 128) {
        int r = i >> 4, c4 = (i & 15) << 2;
        float4 v = *(const float4*)&qkv[(size_t)((qt * 64 + r) * BB + b) * D3 + qoff + c4];
        uint32_t* q = Qs + r * 68 + c4;
        q[0] = f2tf32(v.x * 0.125f); q[1] = f2tf32(v.y * 0.125f);
        q[2] = f2tf32(v.z * 0.125f); q[3] = f2tf32(v.w * 0.125f);
    }

    float m[2] = {-1e30f, -1e30f}, l[2] = {0.f, 0.f};
    float o[8][4];
#pragma unroll
    for (int ni = 0; ni < 8; ++ni)
#pragma unroll
        for (int c = 0; c < 4; ++c) o[ni][c] = 0.0f;

    for (int kt = 0; kt <= qt; ++kt) {
        __syncthreads();
        for (int i = tid; i < 64 * 16; i += 128) {
            int r = i >> 4, c4 = (i & 15) << 2;
            size_t row = (size_t)((kt * 64 + r) * BB + b) * D3;
            float4 kv = *(const float4*)&qkv[row + koff + c4];
            float4 vv = *(const float4*)&qkv[row + voff + c4];
            uint32_t* kp = Ks + r * 68 + c4;
            kp[0] = f2tf32(kv.x); kp[1] = f2tf32(kv.y);
            kp[2] = f2tf32(kv.z); kp[3] = f2tf32(kv.w);
            uint32_t* vp = Vs + r * 72 + c4;
            vp[0] = f2tf32(vv.x); vp[1] = f2tf32(vv.y);
            vp[2] = f2tf32(vv.z); vp[3] = f2tf32(vv.w);
        }
        __syncthreads();

        // S = Q K^T  (warp: 16x64)
        float s[8][4];
#pragma unroll
        for (int ni = 0; ni < 8; ++ni)
#pragma unroll
            for (int c = 0; c < 4; ++c) s[ni][c] = 0.0f;

#pragma unroll
        for (int k8 = 0; k8 < 64; k8 += 8) {
            const uint32_t* qp = Qs + (wr + gid) * 68 + k8 + tig;
            uint32_t a0 = qp[0], a1 = qp[8 * 68], a2 = qp[4], a3 = qp[8 * 68 + 4];
#pragma unroll
            for (int ni = 0; ni < 8; ++ni) {
                const uint32_t* kp = Ks + (ni * 8 + gid) * 68 + k8 + tig;
                MMA_TF32(s[ni][0], s[ni][1], s[ni][2], s[ni][3],
                         a0, a1, a2, a3, kp[0], kp[4 - 4 + 4]);
            }
        }

        // causal mask on diagonal tile
        if (kt == qt) {
#pragma unroll
            for (int ni = 0; ni < 8; ++ni) {
#pragma unroll
                for (int c = 0; c < 4; ++c) {
                    int kl = ni * 8 + 2 * tig + (c & 1);
                    int ql = wr + gid + ((c >> 1) << 3);
                    if (kl > ql) s[ni][c] = -1e30f;
                }
            }
        }

        // online softmax per row-half
#pragma unroll
        for (int hf = 0; hf < 2; ++hf) {
            float mx = -1e30f;
#pragma unroll
            for (int ni = 0; ni < 8; ++ni)
                mx = fmaxf(mx, fmaxf(s[ni][2 * hf], s[ni][2 * hf + 1]));
            mx = fmaxf(mx, __shfl_xor_sync(0xffffffffu, mx, 1));
            mx = fmaxf(mx, __shfl_xor_sync(0xffffffffu, mx, 2));
            float mnew  = fmaxf(m[hf], mx);
            float alpha = __expf(m[hf] - mnew);
            float rs = 0.0f;
            int prow = wr + gid + hf * 8;
#pragma unroll
            for (int ni = 0; ni < 8; ++ni) {
                float p0 = __expf(s[ni][2 * hf]     - mnew);
                float p1 = __expf(s[ni][2 * hf + 1] - mnew);
                rs += p0 + p1;
                uint32_t* pp = Ps + prow * 68 + ni * 8 + 2 * tig;
                pp[0] = f2tf32(p0);
                pp[1] = f2tf32(p1);
            }
            rs += __shfl_xor_sync(0xffffffffu, rs, 1);
            rs += __shfl_xor_sync(0xffffffffu, rs, 2);
            l[hf] = l[hf] * alpha + rs;
            m[hf] = mnew;
#pragma unroll
            for (int ni = 0; ni < 8; ++ni) {
                o[ni][2 * hf]     *= alpha;
                o[ni][2 * hf + 1] *= alpha;
            }
        }
        __syncwarp();

        // O += P V  (warp: 16x64)
#pragma unroll
        for (int k8 = 0; k8 < 64; k8 += 8) {
            const uint32_t* pp = Ps + (wr + gid) * 68 + k8 + tig;
            uint32_t a0 = pp[0], a1 = pp[8 * 68], a2 = pp[4], a3 = pp[8 * 68 + 4];
#pragma unroll
            for (int ni = 0; ni < 8; ++ni) {
                const uint32_t* vp = Vs + (k8 + tig) * 72 + ni * 8 + gid;
                MMA_TF32(o[ni][0], o[ni][1], o[ni][2], o[ni][3],
                         a0, a1, a2, a3, vp[0], vp[4 * 72]);
            }
        }
    }

    // epilogue
#pragma unroll
    for (int hf = 0; hf < 2; ++hf) {
        int row = qt * 64 + wr + gid + hf * 8;
        float inv = 1.0f / l[hf];
        float* op = outp + (size_t)(row * BB + b) * DD + h * HDIM;
#pragma unroll
        for (int ni = 0; ni < 8; ++ni)
            *(float2*)(op + ni * 8 + 2 * tig) =
                make_float2(o[ni][2 * hf] * inv, o[ni][2 * hf + 1] * inv);
    }
}

// ---------------------------------------------------------------------------
// Residual add + LayerNorm over D=1024. One block (256 thr) per row.
// ---------------------------------------------------------------------------
__global__ void __launch_bounds__(256)
add_ln_kernel(const float* __restrict__ y, const float* __restrict__ res,
              const float* __restrict__ g, const float* __restrict__ beta,
              float* __restrict__ out)
{
    const int row = blockIdx.x;
    const int tid = threadIdx.x;

    float4 a = ((const float4*)(y   + (size_t)row * DD))[tid];
    float4 r = ((const float4*)(res + (size_t)row * DD))[tid];
    float v0 = a.x + r.x, v1 = a.y + r.y, v2 = a.z + r.z, v3 = a.w + r.w;

    float s  = v0 + v1 + v2 + v3;
    float ss = v0 * v0 + v1 * v1 + v2 * v2 + v3 * v3;

#pragma unroll
    for (int o = 16; o > 0; o >>= 1) {
        s  += __shfl_xor_sync(0xffffffffu, s,  o);
        ss += __shfl_xor_sync(0xffffffffu, ss, o);
    }
    __shared__ float2 red[8];
    if ((tid & 31) == 0) red[tid >> 5] = make_float2(s, ss);
    __syncthreads();
    float sx = 0.f, sxx = 0.f;
#pragma unroll
    for (int i = 0; i < 8; ++i) { sx += red[i].x; sxx += red[i].y; }

    const float invD = 1.0f / (float)DD;
    float mean = sx * invD;
    float var  = fmaxf(sxx * invD - mean * mean, 0.0f);
    float rstd = rsqrtf(var + 1e-5f);

    float4 gg = ((const float4*)g)[tid];
    float4 bb = ((const float4*)beta)[tid];
    float4 o;
    o.x = (v0 - mean) * rstd * gg.x + bb.x;
    o.y = (v1 - mean) * rstd * gg.y + bb.y;
    o.z = (v2 - mean) * rstd * gg.z + bb.z;
    o.w = (v3 - mean) * rstd * gg.w + bb.w;
    ((float4*)(out + (size_t)row * DD))[tid] = o;
}

// ---------------------------------------------------------------------------
// Launch
// ---------------------------------------------------------------------------
extern "C" void kernel_launch(void* const* d_in, const int* in_sizes, int n_in,
                              void* d_out, int out_size)
{
    const float* x         = (const float*)d_in[0];
    const float* in_proj_w = (const float*)d_in[2];
    const float* in_proj_b = (const float*)d_in[3];
    const float* out_w     = (const float*)d_in[4];
    const float* out_b     = (const float*)d_in[5];
    const float* fc1_w     = (const float*)d_in[6];
    const float* fc1_b     = (const float*)d_in[7];
    const float* fc2_w     = (const float*)d_in[8];
    const float* fc2_b     = (const float*)d_in[9];
    const float* ln1_g     = (const float*)d_in[10];
    const float* ln1_b     = (const float*)d_in[11];
    const float* ln2_g     = (const float*)d_in[12];
    const float* ln2_b     = (const float*)d_in[13];
    float* out = (float*)d_out;

    float *qkv, *attn, *h, *ff, *tmp;
    cudaGetSymbolAddress((void**)&qkv,  g_qkv);
    cudaGetSymbolAddress((void**)&attn, g_attn);
    cudaGetSymbolAddress((void**)&h,    g_h);
    cudaGetSymbolAddress((void**)&ff,   g_ff);
    cudaGetSymbolAddress((void**)&tmp,  g_tmp);

    cudaFuncSetAttribute(gemm_tf32<0>,
                         cudaFuncAttributeMaxDynamicSharedMemorySize, GEMM_SMEM);
    cudaFuncSetAttribute(gemm_tf32<1>,
                         cudaFuncAttributeMaxDynamicSharedMemorySize, GEMM_SMEM);
    cudaFuncSetAttribute(attn_mma,
                         cudaFuncAttributeMaxDynamicSharedMemorySize, ATTN_SMEM);

    gemm_tf32<0><<<dim3(D3 / 128, MM / 128), 256, GEMM_SMEM>>>(
        x, in_proj_w, in_proj_b, qkv, MM, D3, DD);

    attn_mma<<<dim3(TT / 64, HH, BB), 128, ATTN_SMEM>>>(qkv, attn);

    gemm_tf32<0><<<dim3(DD / 128, MM / 128), 256, GEMM_SMEM>>>(
        attn, out_w, out_b, tmp, MM, DD, DD);

    add_ln_kernel<<<MM, 256>>>(tmp, x, ln1_g, ln1_b, h);

    gemm_tf32<1><<<dim3(FFD / 128, MM / 128), 256, GEMM_SMEM>>>(
        h, fc1_w, fc1_b, ff, MM, FFD, DD);

    gemm_tf32<0><<<dim3(DD / 128, MM / 128), 256, GEMM_SMEM>>>(
        ff, fc2_w, fc2_b, tmp, MM, DD, FFD);

    add_ln_kernel<<<MM, 256>>>(tmp, h, ln2_g, ln2_b, out);
}

// round 4
// speedup vs baseline: 2.5189x; 1.0003x over previous
#include <cuda_runtime.h>
#include <cuda_bf16.h>
#include <cstdint>
#include <cstddef>

// ---------------------------------------------------------------------------
// Problem constants
// ---------------------------------------------------------------------------
#define TT   2048
#define BB   2
#define DD   1024
#define HH   16
#define HDIM 64
#define FFD  4096
#define MM   (TT * BB)          // 4096 rows
#define D3   (3 * DD)           // 3072

// ---------------------------------------------------------------------------
// Scratch (device globals; no runtime allocation allowed)
// ---------------------------------------------------------------------------
__device__ float g_qkv [MM * D3];
__device__ float g_attn[MM * DD];
__device__ float g_h   [MM * DD];
__device__ float g_ff  [MM * FFD];
__device__ float g_tmp [MM * DD];

__device__ __forceinline__ float gelu_f(float v) {
    const float c = 0.7978845608028654f;   // sqrt(2/pi)
    float t = tanhf(c * (v + 0.044715f * v * v * v));
    return 0.5f * v * (1.0f + t);
}

__device__ __forceinline__ uint32_t f2tf32(float f) {
    uint32_t u;
    asm("cvt.rna.tf32.f32 %0, %1;" : "=r"(u) : "f"(f));
    return u;
}

#define MMA_TF32(d0,d1,d2,d3,a0,a1,a2,a3,b0,b1)                               \
    asm volatile(                                                             \
        "mma.sync.aligned.m16n8k8.row.col.f32.tf32.tf32.f32 "                 \
        "{%0,%1,%2,%3}, {%4,%5,%6,%7}, {%8,%9}, {%0,%1,%2,%3};\n"             \
        : "+f"(d0), "+f"(d1), "+f"(d2), "+f"(d3)                              \
        : "r"(a0), "r"(a1), "r"(a2), "r"(a3), "r"(b0), "r"(b1))

// ---------------------------------------------------------------------------
// tf32 tensor-core GEMM: C[M,N] = A[M,K] @ W[N,K]^T + bias (opt. GELU)
// 128x128 tile, BK=16, 256 threads (8 warps x 64x32), double-buffered,
// 2 CTAs/SM (40KB smem, <=128 regs).
// ---------------------------------------------------------------------------
#define BK  16
#define LDA 20
#define GEMM_SMEM (2 * 2 * 128 * LDA * 4)   // 40960 bytes

template <int ACT>
__global__ void __launch_bounds__(256, 2)
gemm_tf32(const float* __restrict__ A, const float* __restrict__ W,
          const float* __restrict__ bias, float* __restrict__ C,
          int M, int N, int K)
{
    extern __shared__ uint32_t sm[];
    uint32_t* As = sm;                    // [2][128*LDA]
    uint32_t* Ws = sm + 2 * 128 * LDA;

    const int tid  = threadIdx.x;
    const int m0   = blockIdx.y * 128;
    const int n0   = blockIdx.x * 128;
    const int warp = tid >> 5, lane = tid & 31;
    const int gid  = lane >> 2, tig = lane & 3;
    const int wm   = (warp & 1) * 64;
    const int wn   = (warp >> 1) * 32;

    float acc[4][4][4];
#pragma unroll
    for (int i = 0; i < 4; ++i)
#pragma unroll
        for (int j = 0; j < 4; ++j)
#pragma unroll
            for (int c = 0; c < 4; ++c) acc[i][j][c] = 0.0f;

    // global loads: one row per thread, 16 floats (2 x float4)
    const int lr = tid >> 1;
    const int lc = (tid & 1) << 3;        // 0 or 8
    const float* Ag = A + (size_t)(m0 + lr) * K + lc;
    const float* Wg = W + (size_t)(n0 + lr) * K + lc;

    float4 ra[2], rw[2];

    auto LDG = [&](int k0) {
        ra[0] = *(const float4*)(Ag + k0);
        ra[1] = *(const float4*)(Ag + k0 + 4);
        rw[0] = *(const float4*)(Wg + k0);
        rw[1] = *(const float4*)(Wg + k0 + 4);
    };
    auto STS = [&](int buf) {
        uint32_t* Ab = As + buf * 128 * LDA + lr * LDA + lc;
        uint32_t* Wb = Ws + buf * 128 * LDA + lr * LDA + lc;
        *(uint4*)(Ab)     = make_uint4(f2tf32(ra[0].x), f2tf32(ra[0].y),
                                       f2tf32(ra[0].z), f2tf32(ra[0].w));
        *(uint4*)(Ab + 4) = make_uint4(f2tf32(ra[1].x), f2tf32(ra[1].y),
                                       f2tf32(ra[1].z), f2tf32(ra[1].w));
        *(uint4*)(Wb)     = make_uint4(f2tf32(rw[0].x), f2tf32(rw[0].y),
                                       f2tf32(rw[0].z), f2tf32(rw[0].w));
        *(uint4*)(Wb + 4) = make_uint4(f2tf32(rw[1].x), f2tf32(rw[1].y),
                                       f2tf32(rw[1].z), f2tf32(rw[1].w));
    };
    auto COMPUTE = [&](int buf) {
        const uint32_t* Ab = As + buf * 128 * LDA;
        const uint32_t* Wb = Ws + buf * 128 * LDA;
#pragma unroll
        for (int k8 = 0; k8 < BK; k8 += 8) {
            uint32_t af[4][4], bf[4][2];
#pragma unroll
            for (int mi = 0; mi < 4; ++mi) {
                const uint32_t* p = Ab + (wm + mi * 16 + gid) * LDA + k8 + tig;
                af[mi][0] = p[0];
                af[mi][1] = p[8 * LDA];
                af[mi][2] = p[4];
                af[mi][3] = p[8 * LDA + 4];
            }
#pragma unroll
            for (int ni = 0; ni < 4; ++ni) {
                const uint32_t* p = Wb + (wn + ni * 8 + gid) * LDA + k8 + tig;
                bf[ni][0] = p[0];
                bf[ni][1] = p[4];
            }
#pragma unroll
            for (int mi = 0; mi < 4; ++mi)
#pragma unroll
                for (int ni = 0; ni < 4; ++ni)
                    MMA_TF32(acc[mi][ni][0], acc[mi][ni][1],
                             acc[mi][ni][2], acc[mi][ni][3],
                             af[mi][0], af[mi][1], af[mi][2], af[mi][3],
                             bf[ni][0], bf[ni][1]);
        }
    };

    const int KT = K / BK;
    LDG(0);
    STS(0);
    __syncthreads();
    for (int kt = 0; kt < KT; ++kt) {
        if (kt + 1 < KT) LDG((kt + 1) * BK);
        COMPUTE(kt & 1);
        if (kt + 1 < KT) STS((kt + 1) & 1);
        __syncthreads();
    }

#pragma unroll
    for (int mi = 0; mi < 4; ++mi) {
#pragma unroll
        for (int ni = 0; ni < 4; ++ni) {
            int col = n0 + wn + ni * 8 + 2 * tig;
            float b0 = bias[col], b1 = bias[col + 1];
            int row = m0 + wm + mi * 16 + gid;
            float v0 = acc[mi][ni][0] + b0;
            float v1 = acc[mi][ni][1] + b1;
            float v2 = acc[mi][ni][2] + b0;
            float v3 = acc[mi][ni][3] + b1;
            if (ACT == 1) {
                v0 = gelu_f(v0); v1 = gelu_f(v1);
                v2 = gelu_f(v2); v3 = gelu_f(v3);
            }
            *(float2*)(C + (size_t)row * N + col)       = make_float2(v0, v1);
            *(float2*)(C + (size_t)(row + 8) * N + col) = make_float2(v2, v3);
        }
    }
}

// ---------------------------------------------------------------------------
// Flash attention (causal) on tf32 tensor cores.
// Grid (qt=32, h=16, b=2), 128 threads (4 warps). BM=64, BN=64, HD=64.
// Warp w owns q-rows [w*16, w*16+16). Dynamic smem 70656 B.
// ---------------------------------------------------------------------------
#define ATTN_SMEM ((64 * 68 * 3 + 64 * 72) * 4)

__global__ void __launch_bounds__(128)
attn_mma(const float* __restrict__ qkv, float* __restrict__ outp)
{
    extern __shared__ uint32_t asm_[];
    uint32_t* Qs = asm_;                    // [64][68]
    uint32_t* Ks = Qs + 64 * 68;            // [64][68]
    uint32_t* Ps = Ks + 64 * 68;            // [64][68]
    uint32_t* Vs = Ps + 64 * 68;            // [64][72]

    const int qt = blockIdx.x, h = blockIdx.y, b = blockIdx.z;
    const int tid = threadIdx.x;
    const int warp = tid >> 5, lane = tid & 31;
    const int gid = lane >> 2, tig = lane & 3;
    const int wr = warp * 16;

    const int qoff = h * HDIM;
    const int koff = DD + h * HDIM;
    const int voff = 2 * DD + h * HDIM;

    // load Q tile (scaled by 0.125, tf32-rounded)
    for (int i = tid; i < 64 * 16; i += 128) {
        int r = i >> 4, c4 = (i & 15) << 2;
        float4 v = *(const float4*)&qkv[(size_t)((qt * 64 + r) * BB + b) * D3 + qoff + c4];
        uint32_t* q = Qs + r * 68 + c4;
        q[0] = f2tf32(v.x * 0.125f); q[1] = f2tf32(v.y * 0.125f);
        q[2] = f2tf32(v.z * 0.125f); q[3] = f2tf32(v.w * 0.125f);
    }

    float m[2] = {-1e30f, -1e30f}, l[2] = {0.f, 0.f};
    float o[8][4];
#pragma unroll
    for (int ni = 0; ni < 8; ++ni)
#pragma unroll
        for (int c = 0; c < 4; ++c) o[ni][c] = 0.0f;

    for (int kt = 0; kt <= qt; ++kt) {
        __syncthreads();
        for (int i = tid; i < 64 * 16; i += 128) {
            int r = i >> 4, c4 = (i & 15) << 2;
            size_t row = (size_t)((kt * 64 + r) * BB + b) * D3;
            float4 kv = *(const float4*)&qkv[row + koff + c4];
            float4 vv = *(const float4*)&qkv[row + voff + c4];
            uint32_t* kp = Ks + r * 68 + c4;
            kp[0] = f2tf32(kv.x); kp[1] = f2tf32(kv.y);
            kp[2] = f2tf32(kv.z); kp[3] = f2tf32(kv.w);
            uint32_t* vp = Vs + r * 72 + c4;
            vp[0] = f2tf32(vv.x); vp[1] = f2tf32(vv.y);
            vp[2] = f2tf32(vv.z); vp[3] = f2tf32(vv.w);
        }
        __syncthreads();

        // S = Q K^T  (warp: 16x64)
        float s[8][4];
#pragma unroll
        for (int ni = 0; ni < 8; ++ni)
#pragma unroll
            for (int c = 0; c < 4; ++c) s[ni][c] = 0.0f;

#pragma unroll
        for (int k8 = 0; k8 < 64; k8 += 8) {
            const uint32_t* qp = Qs + (wr + gid) * 68 + k8 + tig;
            uint32_t a0 = qp[0], a1 = qp[8 * 68], a2 = qp[4], a3 = qp[8 * 68 + 4];
#pragma unroll
            for (int ni = 0; ni < 8; ++ni) {
                const uint32_t* kp = Ks + (ni * 8 + gid) * 68 + k8 + tig;
                MMA_TF32(s[ni][0], s[ni][1], s[ni][2], s[ni][3],
                         a0, a1, a2, a3, kp[0], kp[4 - 4 + 4]);
            }
        }

        // causal mask on diagonal tile
        if (kt == qt) {
#pragma unroll
            for (int ni = 0; ni < 8; ++ni) {
#pragma unroll
                for (int c = 0; c < 4; ++c) {
                    int kl = ni * 8 + 2 * tig + (c & 1);
                    int ql = wr + gid + ((c >> 1) << 3);
                    if (kl > ql) s[ni][c] = -1e30f;
                }
            }
        }

        // online softmax per row-half
#pragma unroll
        for (int hf = 0; hf < 2; ++hf) {
            float mx = -1e30f;
#pragma unroll
            for (int ni = 0; ni < 8; ++ni)
                mx = fmaxf(mx, fmaxf(s[ni][2 * hf], s[ni][2 * hf + 1]));
            mx = fmaxf(mx, __shfl_xor_sync(0xffffffffu, mx, 1));
            mx = fmaxf(mx, __shfl_xor_sync(0xffffffffu, mx, 2));
            float mnew  = fmaxf(m[hf], mx);
            float alpha = __expf(m[hf] - mnew);
            float rs = 0.0f;
            int prow = wr + gid + hf * 8;
#pragma unroll
            for (int ni = 0; ni < 8; ++ni) {
                float p0 = __expf(s[ni][2 * hf]     - mnew);
                float p1 = __expf(s[ni][2 * hf + 1] - mnew);
                rs += p0 + p1;
                uint32_t* pp = Ps + prow * 68 + ni * 8 + 2 * tig;
                pp[0] = f2tf32(p0);
                pp[1] = f2tf32(p1);
            }
            rs += __shfl_xor_sync(0xffffffffu, rs, 1);
            rs += __shfl_xor_sync(0xffffffffu, rs, 2);
            l[hf] = l[hf] * alpha + rs;
            m[hf] = mnew;
#pragma unroll
            for (int ni = 0; ni < 8; ++ni) {
                o[ni][2 * hf]     *= alpha;
                o[ni][2 * hf + 1] *= alpha;
            }
        }
        __syncwarp();

        // O += P V  (warp: 16x64)
#pragma unroll
        for (int k8 = 0; k8 < 64; k8 += 8) {
            const uint32_t* pp = Ps + (wr + gid) * 68 + k8 + tig;
            uint32_t a0 = pp[0], a1 = pp[8 * 68], a2 = pp[4], a3 = pp[8 * 68 + 4];
#pragma unroll
            for (int ni = 0; ni < 8; ++ni) {
                const uint32_t* vp = Vs + (k8 + tig) * 72 + ni * 8 + gid;
                MMA_TF32(o[ni][0], o[ni][1], o[ni][2], o[ni][3],
                         a0, a1, a2, a3, vp[0], vp[4 * 72]);
            }
        }
    }

    // epilogue
#pragma unroll
    for (int hf = 0; hf < 2; ++hf) {
        int row = qt * 64 + wr + gid + hf * 8;
        float inv = 1.0f / l[hf];
        float* op = outp + (size_t)(row * BB + b) * DD + h * HDIM;
#pragma unroll
        for (int ni = 0; ni < 8; ++ni)
            *(float2*)(op + ni * 8 + 2 * tig) =
                make_float2(o[ni][2 * hf] * inv, o[ni][2 * hf + 1] * inv);
    }
}

// ---------------------------------------------------------------------------
// Residual add + LayerNorm over D=1024. One block (256 thr) per row.
// ---------------------------------------------------------------------------
__global__ void __launch_bounds__(256)
add_ln_kernel(const float* __restrict__ y, const float* __restrict__ res,
              const float* __restrict__ g, const float* __restrict__ beta,
              float* __restrict__ out)
{
    const int row = blockIdx.x;
    const int tid = threadIdx.x;

    float4 a = ((const float4*)(y   + (size_t)row * DD))[tid];
    float4 r = ((const float4*)(res + (size_t)row * DD))[tid];
    float v0 = a.x + r.x, v1 = a.y + r.y, v2 = a.z + r.z, v3 = a.w + r.w;

    float s  = v0 + v1 + v2 + v3;
    float ss = v0 * v0 + v1 * v1 + v2 * v2 + v3 * v3;

#pragma unroll
    for (int o = 16; o > 0; o >>= 1) {
        s  += __shfl_xor_sync(0xffffffffu, s,  o);
        ss += __shfl_xor_sync(0xffffffffu, ss, o);
    }
    __shared__ float2 red[8];
    if ((tid & 31) == 0) red[tid >> 5] = make_float2(s, ss);
    __syncthreads();
    float sx = 0.f, sxx = 0.f;
#pragma unroll
    for (int i = 0; i < 8; ++i) { sx += red[i].x; sxx += red[i].y; }

    const float invD = 1.0f / (float)DD;
    float mean = sx * invD;
    float var  = fmaxf(sxx * invD - mean * mean, 0.0f);
    float rstd = rsqrtf(var + 1e-5f);

    float4 gg = ((const float4*)g)[tid];
    float4 bb = ((const float4*)beta)[tid];
    float4 o;
    o.x = (v0 - mean) * rstd * gg.x + bb.x;
    o.y = (v1 - mean) * rstd * gg.y + bb.y;
    o.z = (v2 - mean) * rstd * gg.z + bb.z;
    o.w = (v3 - mean) * rstd * gg.w + bb.w;
    ((float4*)(out + (size_t)row * DD))[tid] = o;
}

// ---------------------------------------------------------------------------
// Launch
// ---------------------------------------------------------------------------
extern "C" void kernel_launch(void* const* d_in, const int* in_sizes, int n_in,
                              void* d_out, int out_size)
{
    const float* x         = (const float*)d_in[0];
    const float* in_proj_w = (const float*)d_in[2];
    const float* in_proj_b = (const float*)d_in[3];
    const float* out_w     = (const float*)d_in[4];
    const float* out_b     = (const float*)d_in[5];
    const float* fc1_w     = (const float*)d_in[6];
    const float* fc1_b     = (const float*)d_in[7];
    const float* fc2_w     = (const float*)d_in[8];
    const float* fc2_b     = (const float*)d_in[9];
    const float* ln1_g     = (const float*)d_in[10];
    const float* ln1_b     = (const float*)d_in[11];
    const float* ln2_g     = (const float*)d_in[12];
    const float* ln2_b     = (const float*)d_in[13];
    float* out = (float*)d_out;

    float *qkv, *attn, *h, *ff, *tmp;
    cudaGetSymbolAddress((void**)&qkv,  g_qkv);
    cudaGetSymbolAddress((void**)&attn, g_attn);
    cudaGetSymbolAddress((void**)&h,    g_h);
    cudaGetSymbolAddress((void**)&ff,   g_ff);
    cudaGetSymbolAddress((void**)&tmp,  g_tmp);

    cudaFuncSetAttribute(gemm_tf32<0>,
                         cudaFuncAttributeMaxDynamicSharedMemorySize, GEMM_SMEM);
    cudaFuncSetAttribute(gemm_tf32<1>,
                         cudaFuncAttributeMaxDynamicSharedMemorySize, GEMM_SMEM);
    cudaFuncSetAttribute(attn_mma,
                         cudaFuncAttributeMaxDynamicSharedMemorySize, ATTN_SMEM);

    gemm_tf32<0><<<dim3(D3 / 128, MM / 128), 256, GEMM_SMEM>>>(
        x, in_proj_w, in_proj_b, qkv, MM, D3, DD);

    attn_mma<<<dim3(TT / 64, HH, BB), 128, ATTN_SMEM>>>(qkv, attn);

    gemm_tf32<0><<<dim3(DD / 128, MM / 128), 256, GEMM_SMEM>>>(
        attn, out_w, out_b, tmp, MM, DD, DD);

    add_ln_kernel<<<MM, 256>>>(tmp, x, ln1_g, ln1_b, h);

    gemm_tf32<1><<<dim3(FFD / 128, MM / 128), 256, GEMM_SMEM>>>(
        h, fc1_w, fc1_b, ff, MM, FFD, DD);

    gemm_tf32<0><<<dim3(DD / 128, MM / 128), 256, GEMM_SMEM>>>(
        ff, fc2_w, fc2_b, tmp, MM, DD, FFD);

    add_ln_kernel<<<MM, 256>>>(tmp, h, ln2_g, ln2_b, out);
}

// round 5
// speedup vs baseline: 3.2468x; 1.2890x over previous
#include <cuda_runtime.h>
#include <cuda_bf16.h>
#include <cstdint>
#include <cstddef>

// ---------------------------------------------------------------------------
// Problem constants
// ---------------------------------------------------------------------------
#define TT   2048
#define BB   2
#define DD   1024
#define HH   16
#define HDIM 64
#define FFD  4096
#define MM   (TT * BB)          // 4096 rows
#define D3   (3 * DD)           // 3072

// ---------------------------------------------------------------------------
// Scratch (device globals; no runtime allocation allowed)
// ---------------------------------------------------------------------------
__device__ float g_qkv [MM * D3];
__device__ float g_attn[MM * DD];
__device__ float g_h   [MM * DD];
__device__ float g_ff  [MM * FFD];
__device__ float g_tmp [MM * DD];

__device__ __forceinline__ float gelu_f(float v) {
    const float c = 0.7978845608028654f;   // sqrt(2/pi)
    float t = tanhf(c * (v + 0.044715f * v * v * v));
    return 0.5f * v * (1.0f + t);
}

__device__ __forceinline__ uint32_t f2tf32(float f) {
    uint32_t u;
    asm("cvt.rna.tf32.f32 %0, %1;" : "=r"(u) : "f"(f));
    return u;
}

#define MMA_TF32(d0,d1,d2,d3,a0,a1,a2,a3,b0,b1)                               \
    asm volatile(                                                             \
        "mma.sync.aligned.m16n8k8.row.col.f32.tf32.tf32.f32 "                 \
        "{%0,%1,%2,%3}, {%4,%5,%6,%7}, {%8,%9}, {%0,%1,%2,%3};\n"             \
        : "+f"(d0), "+f"(d1), "+f"(d2), "+f"(d3)                              \
        : "r"(a0), "r"(a1), "r"(a2), "r"(a3), "r"(b0), "r"(b1))

#define LDSM4(r0,r1,r2,r3,addr)                                               \
    asm volatile("ldmatrix.sync.aligned.m8n8.x4.shared.b16 {%0,%1,%2,%3}, [%4];" \
        : "=r"(r0), "=r"(r1), "=r"(r2), "=r"(r3) : "r"(addr))

__device__ __forceinline__ void cp16(uint32_t dst, const void* src) {
    asm volatile("cp.async.cg.shared.global [%0], [%1], 16;\n"
                 :: "r"(dst), "l"(src));
}
#define CP_COMMIT() asm volatile("cp.async.commit_group;\n")
#define CP_WAIT(n)  asm volatile("cp.async.wait_group %0;\n" :: "n"(n))

// ---------------------------------------------------------------------------
// tf32 GEMM v2: C[M,N] = A[M,K] @ W[N,K]^T + bias (opt. GELU)
// 128x128 tile, BK=16, 3-stage cp.async pipeline, ldmatrix fragments,
// raw-fp32-as-tf32 (hw truncation). 256 threads, 2 CTAs/SM.
// ---------------------------------------------------------------------------
#define BK      16
#define LDA     20
#define SW      (128 * LDA)                   // words per operand per stage
#define STAGES  3
#define GEMM_SMEM (STAGES * 2 * SW * 4)       // 61440 bytes

template <int ACT>
__global__ void __launch_bounds__(256, 2)
gemm_tf32(const float* __restrict__ A, const float* __restrict__ W,
          const float* __restrict__ bias, float* __restrict__ C,
          int M, int N, int K)
{
    extern __shared__ uint32_t sm[];
    const uint32_t smem0 = (uint32_t)__cvta_generic_to_shared(sm);

    const int tid  = threadIdx.x;
    const int m0   = blockIdx.y * 128;
    const int n0   = blockIdx.x * 128;
    const int warp = tid >> 5, lane = tid & 31;
    const int gid  = lane >> 2, tig = lane & 3;
    const int wm   = (warp & 1) * 64;
    const int wn   = (warp >> 1) * 32;

    float acc[4][4][4];
#pragma unroll
    for (int i = 0; i < 4; ++i)
#pragma unroll
        for (int j = 0; j < 4; ++j)
#pragma unroll
            for (int c = 0; c < 4; ++c) acc[i][j][c] = 0.0f;

    // cp.async assignment: one 128-row x 16-col chunk per operand;
    // thread -> row lr, word-col lc (two 16B chunks).
    const int lr = tid >> 1;
    const int lc = (tid & 1) << 3;            // 0 or 8
    const float* Ag = A + (size_t)(m0 + lr) * K + lc;
    const float* Wg = W + (size_t)(n0 + lr) * K + lc;
    const uint32_t sA = smem0 + (uint32_t)(lr * LDA + lc) * 4u;
    const uint32_t sW = sA + SW * 4u;

    auto LOAD = [&](int s, int k0) {
        uint32_t off = (uint32_t)s * 2u * SW * 4u;
        cp16(sA + off,      Ag + k0);
        cp16(sA + off + 16, Ag + k0 + 4);
        cp16(sW + off,      Wg + k0);
        cp16(sW + off + 16, Wg + k0 + 4);
        CP_COMMIT();
    };

    // ldmatrix per-lane base addresses
    const int aRow = wm + (lane & 15);
    const int aCol = (lane & 16) >> 2;                       // 0 or 4
    const uint32_t aBase = smem0 + (uint32_t)(aRow * LDA + aCol) * 4u;
    const int bRow = wn + ((lane & 16) >> 1) + (lane & 7);   // spans 16 n-rows
    const int bCol = (lane & 8) >> 1;                        // 0 or 4
    const uint32_t bBase = smem0 + SW * 4u + (uint32_t)(bRow * LDA + bCol) * 4u;

    auto COMPUTE = [&](int s) {
        const uint32_t off = (uint32_t)s * 2u * SW * 4u;
#pragma unroll
        for (int k8 = 0; k8 < BK; k8 += 8) {
            uint32_t af[4][4], bf[4][2];
#pragma unroll
            for (int mi = 0; mi < 4; ++mi)
                LDSM4(af[mi][0], af[mi][1], af[mi][2], af[mi][3],
                      aBase + off + (uint32_t)(mi * 16 * LDA + k8) * 4u);
#pragma unroll
            for (int p = 0; p < 2; ++p)
                LDSM4(bf[2*p][0], bf[2*p][1], bf[2*p+1][0], bf[2*p+1][1],
                      bBase + off + (uint32_t)(p * 16 * LDA + k8) * 4u);
#pragma unroll
            for (int mi = 0; mi < 4; ++mi)
#pragma unroll
                for (int ni = 0; ni < 4; ++ni)
                    MMA_TF32(acc[mi][ni][0], acc[mi][ni][1],
                             acc[mi][ni][2], acc[mi][ni][3],
                             af[mi][0], af[mi][1], af[mi][2], af[mi][3],
                             bf[ni][0], bf[ni][1]);
        }
    };

    const int KT = K / BK;
    LOAD(0, 0);
    LOAD(1, BK);
    for (int kt = 0; kt < KT; ++kt) {
        CP_WAIT(1);            // chunk kt landed (this thread's groups)
        __syncthreads();       // visible to all; stage (kt-1)%3 free for reuse
        if (kt + 2 < KT) LOAD((kt + 2) % STAGES, (kt + 2) * BK);
        COMPUTE(kt % STAGES);
    }
    __syncthreads();

    // epilogue: bias (+gelu) and store
#pragma unroll
    for (int mi = 0; mi < 4; ++mi) {
#pragma unroll
        for (int ni = 0; ni < 4; ++ni) {
            int col = n0 + wn + ni * 8 + 2 * tig;
            float b0 = bias[col], b1 = bias[col + 1];
            int row = m0 + wm + mi * 16 + gid;
            float v0 = acc[mi][ni][0] + b0;
            float v1 = acc[mi][ni][1] + b1;
            float v2 = acc[mi][ni][2] + b0;
            float v3 = acc[mi][ni][3] + b1;
            if (ACT == 1) {
                v0 = gelu_f(v0); v1 = gelu_f(v1);
                v2 = gelu_f(v2); v3 = gelu_f(v3);
            }
            *(float2*)(C + (size_t)row * N + col)       = make_float2(v0, v1);
            *(float2*)(C + (size_t)(row + 8) * N + col) = make_float2(v2, v3);
        }
    }
}

// ---------------------------------------------------------------------------
// Flash attention (causal) on tf32 tensor cores. Unchanged from R3 (passing).
// Grid (qt=32, h=16, b=2), 128 threads (4 warps). BM=64, BN=64, HD=64.
// ---------------------------------------------------------------------------
#define ATTN_SMEM ((64 * 68 * 3 + 64 * 72) * 4)

__global__ void __launch_bounds__(128)
attn_mma(const float* __restrict__ qkv, float* __restrict__ outp)
{
    extern __shared__ uint32_t asm_[];
    uint32_t* Qs = asm_;                    // [64][68]
    uint32_t* Ks = Qs + 64 * 68;            // [64][68]
    uint32_t* Ps = Ks + 64 * 68;            // [64][68]
    uint32_t* Vs = Ps + 64 * 68;            // [64][72]

    const int qt = blockIdx.x, h = blockIdx.y, b = blockIdx.z;
    const int tid = threadIdx.x;
    const int warp = tid >> 5, lane = tid & 31;
    const int gid = lane >> 2, tig = lane & 3;
    const int wr = warp * 16;

    const int qoff = h * HDIM;
    const int koff = DD + h * HDIM;
    const int voff = 2 * DD + h * HDIM;

    for (int i = tid; i < 64 * 16; i += 128) {
        int r = i >> 4, c4 = (i & 15) << 2;
        float4 v = *(const float4*)&qkv[(size_t)((qt * 64 + r) * BB + b) * D3 + qoff + c4];
        uint32_t* q = Qs + r * 68 + c4;
        q[0] = f2tf32(v.x * 0.125f); q[1] = f2tf32(v.y * 0.125f);
        q[2] = f2tf32(v.z * 0.125f); q[3] = f2tf32(v.w * 0.125f);
    }

    float m[2] = {-1e30f, -1e30f}, l[2] = {0.f, 0.f};
    float o[8][4];
#pragma unroll
    for (int ni = 0; ni < 8; ++ni)
#pragma unroll
        for (int c = 0; c < 4; ++c) o[ni][c] = 0.0f;

    for (int kt = 0; kt <= qt; ++kt) {
        __syncthreads();
        for (int i = tid; i < 64 * 16; i += 128) {
            int r = i >> 4, c4 = (i & 15) << 2;
            size_t row = (size_t)((kt * 64 + r) * BB + b) * D3;
            float4 kv = *(const float4*)&qkv[row + koff + c4];
            float4 vv = *(const float4*)&qkv[row + voff + c4];
            uint32_t* kp = Ks + r * 68 + c4;
            kp[0] = f2tf32(kv.x); kp[1] = f2tf32(kv.y);
            kp[2] = f2tf32(kv.z); kp[3] = f2tf32(kv.w);
            uint32_t* vp = Vs + r * 72 + c4;
            vp[0] = f2tf32(vv.x); vp[1] = f2tf32(vv.y);
            vp[2] = f2tf32(vv.z); vp[3] = f2tf32(vv.w);
        }
        __syncthreads();

        float s[8][4];
#pragma unroll
        for (int ni = 0; ni < 8; ++ni)
#pragma unroll
            for (int c = 0; c < 4; ++c) s[ni][c] = 0.0f;

#pragma unroll
        for (int k8 = 0; k8 < 64; k8 += 8) {
            const uint32_t* qp = Qs + (wr + gid) * 68 + k8 + tig;
            uint32_t a0 = qp[0], a1 = qp[8 * 68], a2 = qp[4], a3 = qp[8 * 68 + 4];
#pragma unroll
            for (int ni = 0; ni < 8; ++ni) {
                const uint32_t* kp = Ks + (ni * 8 + gid) * 68 + k8 + tig;
                MMA_TF32(s[ni][0], s[ni][1], s[ni][2], s[ni][3],
                         a0, a1, a2, a3, kp[0], kp[4]);
            }
        }

        if (kt == qt) {
#pragma unroll
            for (int ni = 0; ni < 8; ++ni) {
#pragma unroll
                for (int c = 0; c < 4; ++c) {
                    int kl = ni * 8 + 2 * tig + (c & 1);
                    int ql = wr + gid + ((c >> 1) << 3);
                    if (kl > ql) s[ni][c] = -1e30f;
                }
            }
        }

#pragma unroll
        for (int hf = 0; hf < 2; ++hf) {
            float mx = -1e30f;
#pragma unroll
            for (int ni = 0; ni < 8; ++ni)
                mx = fmaxf(mx, fmaxf(s[ni][2 * hf], s[ni][2 * hf + 1]));
            mx = fmaxf(mx, __shfl_xor_sync(0xffffffffu, mx, 1));
            mx = fmaxf(mx, __shfl_xor_sync(0xffffffffu, mx, 2));
            float mnew  = fmaxf(m[hf], mx);
            float alpha = __expf(m[hf] - mnew);
            float rs = 0.0f;
            int prow = wr + gid + hf * 8;
#pragma unroll
            for (int ni = 0; ni < 8; ++ni) {
                float p0 = __expf(s[ni][2 * hf]     - mnew);
                float p1 = __expf(s[ni][2 * hf + 1] - mnew);
                rs += p0 + p1;
                uint32_t* pp = Ps + prow * 68 + ni * 8 + 2 * tig;
                pp[0] = f2tf32(p0);
                pp[1] = f2tf32(p1);
            }
            rs += __shfl_xor_sync(0xffffffffu, rs, 1);
            rs += __shfl_xor_sync(0xffffffffu, rs, 2);
            l[hf] = l[hf] * alpha + rs;
            m[hf] = mnew;
#pragma unroll
            for (int ni = 0; ni < 8; ++ni) {
                o[ni][2 * hf]     *= alpha;
                o[ni][2 * hf + 1] *= alpha;
            }
        }
        __syncwarp();

#pragma unroll
        for (int k8 = 0; k8 < 64; k8 += 8) {
            const uint32_t* pp = Ps + (wr + gid) * 68 + k8 + tig;
            uint32_t a0 = pp[0], a1 = pp[8 * 68], a2 = pp[4], a3 = pp[8 * 68 + 4];
#pragma unroll
            for (int ni = 0; ni < 8; ++ni) {
                const uint32_t* vp = Vs + (k8 + tig) * 72 + ni * 8 + gid;
                MMA_TF32(o[ni][0], o[ni][1], o[ni][2], o[ni][3],
                         a0, a1, a2, a3, vp[0], vp[4 * 72]);
            }
        }
    }

#pragma unroll
    for (int hf = 0; hf < 2; ++hf) {
        int row = qt * 64 + wr + gid + hf * 8;
        float inv = 1.0f / l[hf];
        float* op = outp + (size_t)(row * BB + b) * DD + h * HDIM;
#pragma unroll
        for (int ni = 0; ni < 8; ++ni)
            *(float2*)(op + ni * 8 + 2 * tig) =
                make_float2(o[ni][2 * hf] * inv, o[ni][2 * hf + 1] * inv);
    }
}

// ---------------------------------------------------------------------------
// Residual add + LayerNorm over D=1024. One block (256 thr) per row.
// ---------------------------------------------------------------------------
__global__ void __launch_bounds__(256)
add_ln_kernel(const float* __restrict__ y, const float* __restrict__ res,
              const float* __restrict__ g, const float* __restrict__ beta,
              float* __restrict__ out)
{
    const int row = blockIdx.x;
    const int tid = threadIdx.x;

    float4 a = ((const float4*)(y   + (size_t)row * DD))[tid];
    float4 r = ((const float4*)(res + (size_t)row * DD))[tid];
    float v0 = a.x + r.x, v1 = a.y + r.y, v2 = a.z + r.z, v3 = a.w + r.w;

    float s  = v0 + v1 + v2 + v3;
    float ss = v0 * v0 + v1 * v1 + v2 * v2 + v3 * v3;

#pragma unroll
    for (int o = 16; o > 0; o >>= 1) {
        s  += __shfl_xor_sync(0xffffffffu, s,  o);
        ss += __shfl_xor_sync(0xffffffffu, ss, o);
    }
    __shared__ float2 red[8];
    if ((tid & 31) == 0) red[tid >> 5] = make_float2(s, ss);
    __syncthreads();
    float sx = 0.f, sxx = 0.f;
#pragma unroll
    for (int i = 0; i < 8; ++i) { sx += red[i].x; sxx += red[i].y; }

    const float invD = 1.0f / (float)DD;
    float mean = sx * invD;
    float var  = fmaxf(sxx * invD - mean * mean, 0.0f);
    float rstd = rsqrtf(var + 1e-5f);

    float4 gg = ((const float4*)g)[tid];
    float4 bb = ((const float4*)beta)[tid];
    float4 o;
    o.x = (v0 - mean) * rstd * gg.x + bb.x;
    o.y = (v1 - mean) * rstd * gg.y + bb.y;
    o.z = (v2 - mean) * rstd * gg.z + bb.z;
    o.w = (v3 - mean) * rstd * gg.w + bb.w;
    ((float4*)(out + (size_t)row * DD))[tid] = o;
}

// ---------------------------------------------------------------------------
// Launch
// ---------------------------------------------------------------------------
extern "C" void kernel_launch(void* const* d_in, const int* in_sizes, int n_in,
                              void* d_out, int out_size)
{
    const float* x         = (const float*)d_in[0];
    const float* in_proj_w = (const float*)d_in[2];
    const float* in_proj_b = (const float*)d_in[3];
    const float* out_w     = (const float*)d_in[4];
    const float* out_b     = (const float*)d_in[5];
    const float* fc1_w     = (const float*)d_in[6];
    const float* fc1_b     = (const float*)d_in[7];
    const float* fc2_w     = (const float*)d_in[8];
    const float* fc2_b     = (const float*)d_in[9];
    const float* ln1_g     = (const float*)d_in[10];
    const float* ln1_b     = (const float*)d_in[11];
    const float* ln2_g     = (const float*)d_in[12];
    const float* ln2_b     = (const float*)d_in[13];
    float* out = (float*)d_out;

    float *qkv, *attn, *h, *ff, *tmp;
    cudaGetSymbolAddress((void**)&qkv,  g_qkv);
    cudaGetSymbolAddress((void**)&attn, g_attn);
    cudaGetSymbolAddress((void**)&h,    g_h);
    cudaGetSymbolAddress((void**)&ff,   g_ff);
    cudaGetSymbolAddress((void**)&tmp,  g_tmp);

    cudaFuncSetAttribute(gemm_tf32<0>,
                         cudaFuncAttributeMaxDynamicSharedMemorySize, GEMM_SMEM);
    cudaFuncSetAttribute(gemm_tf32<1>,
                         cudaFuncAttributeMaxDynamicSharedMemorySize, GEMM_SMEM);
    cudaFuncSetAttribute(attn_mma,
                         cudaFuncAttributeMaxDynamicSharedMemorySize, ATTN_SMEM);

    gemm_tf32<0><<<dim3(D3 / 128, MM / 128), 256, GEMM_SMEM>>>(
        x, in_proj_w, in_proj_b, qkv, MM, D3, DD);

    attn_mma<<<dim3(TT / 64, HH, BB), 128, ATTN_SMEM>>>(qkv, attn);

    gemm_tf32<0><<<dim3(DD / 128, MM / 128), 256, GEMM_SMEM>>>(
        attn, out_w, out_b, tmp, MM, DD, DD);

    add_ln_kernel<<<MM, 256>>>(tmp, x, ln1_g, ln1_b, h);

    gemm_tf32<1><<<dim3(FFD / 128, MM / 128), 256, GEMM_SMEM>>>(
        h, fc1_w, fc1_b, ff, MM, FFD, DD);

    gemm_tf32<0><<<dim3(DD / 128, MM / 128), 256, GEMM_SMEM>>>(
        ff, fc2_w, fc2_b, tmp, MM, DD, FFD);

    add_ln_kernel<<<MM, 256>>>(tmp, h, ln2_g, ln2_b, out);
}